// round 3
// baseline (speedup 1.0000x reference)
#include <cuda_runtime.h>
#include <mma.h>
#include <math.h>

using namespace nvcuda;

#define NTOK 8192
#define DIM  384
#define NEXP 8
#define HID  1536
#define OUTD 384
#define NPAIR (NTOK * 2)

#define BM 128
#define BN 64
#define KC 32
#define LDA 40   // KC + 8 pad, keeps 32B alignment for wmma (40*4=160B rows)
#define LDB 72   // BN + 8 pad (72*4=288B rows)
#define LDO 72

// ---------------- device scratch (no allocations allowed) ----------------
__device__ int    g_counts[NEXP];
__device__ int    g_list[NEXP * NTOK];       // packed token*2 + slot
__device__ float2 g_gates[NTOK];
__device__ float  g_h[(size_t)NPAIR * HID];  // ~100 MB, tf32-rounded activations
__device__ float  g_y[(size_t)NPAIR * OUTD]; // ~25 MB, gated expert outputs

// ---------------- kernels ----------------
__global__ void zero_counts_kernel() {
    if (threadIdx.x < NEXP) g_counts[threadIdx.x] = 0;
}

__global__ void router_kernel(const float* __restrict__ x,
                              const float* __restrict__ Wg,
                              const float* __restrict__ bg) {
    int warp = (blockIdx.x * blockDim.x + threadIdx.x) >> 5;
    int lane = threadIdx.x & 31;
    if (warp >= NTOK) return;

    const float* xr = x + (size_t)warp * DIM;
    float acc[NEXP];
#pragma unroll
    for (int e = 0; e < NEXP; e++) acc[e] = 0.f;

    for (int d = lane; d < DIM; d += 32) {
        float xv = xr[d];
        const float* wr = Wg + d * NEXP;
#pragma unroll
        for (int e = 0; e < NEXP; e++) acc[e] += xv * wr[e];
    }
#pragma unroll
    for (int e = 0; e < NEXP; e++) {
#pragma unroll
        for (int off = 16; off > 0; off >>= 1)
            acc[e] += __shfl_xor_sync(0xffffffffu, acc[e], off);
    }
    if (lane == 0) {
        float v0 = -1e30f, v1 = -1e30f;
        int   i0 = 0,      i1 = 0;
#pragma unroll
        for (int e = 0; e < NEXP; e++) {
            float v = acc[e] + bg[e];
            if (v > v0)      { v1 = v0; i1 = i0; v0 = v; i0 = e; }
            else if (v > v1) { v1 = v;  i1 = e; }
        }
        // softmax over the two selected logits (others are -inf -> 0)
        float e1 = expf(v1 - v0);
        float inv = 1.0f / (1.0f + e1);
        g_gates[warp] = make_float2(inv, e1 * inv);

        int p0 = atomicAdd(&g_counts[i0], 1);
        g_list[i0 * NTOK + p0] = warp * 2;
        int p1 = atomicAdd(&g_counts[i1], 1);
        g_list[i1 * NTOK + p1] = warp * 2 + 1;
    }
}

// GEMM1: h = gelu(gather(x) @ W1[e] + b1[e]), stored tf32-rounded at g_h[pair]
__global__ void __launch_bounds__(256)
gemm1_kernel(const float* __restrict__ x,
             const float* __restrict__ W1,
             const float* __restrict__ b1) {
    const int e  = blockIdx.z;
    const int M  = g_counts[e];
    const int m0 = blockIdx.x * BM;
    if (m0 >= M) return;
    const int n0 = blockIdx.y * BN;

    __shared__ __align__(32) float smem[BM * LDO];  // 9216 floats, reused as sOut
    float* sA = smem;                  // BM*LDA = 5120
    float* sB = smem + BM * LDA;       // 32*LDB = 2304 (total 7424 <= 9216)
    __shared__ int sEntry[BM];

    const int tid = threadIdx.x;
    if (tid < BM) {
        int r = m0 + tid;
        sEntry[tid] = (r < M) ? g_list[e * NTOK + r] : -1;
    }
    __syncthreads();

    const float* W1e = W1 + (size_t)e * DIM * HID;

    wmma::fragment<wmma::accumulator, 16, 16, 8, float> c[2][2];
#pragma unroll
    for (int i = 0; i < 2; i++)
#pragma unroll
        for (int j = 0; j < 2; j++) wmma::fill_fragment(c[i][j], 0.f);

    const int w  = tid >> 5;
    const int wm = (w & 3) * 32;   // 0..96
    const int wn = (w >> 2) * 32;  // 0,32

    for (int k0 = 0; k0 < DIM; k0 += KC) {
        for (int idx = tid; idx < BM * KC; idx += 256) {
            int r = idx >> 5, cc = idx & 31;
            int entry = sEntry[r];
            float v = 0.f;
            if (entry >= 0) v = x[(size_t)(entry >> 1) * DIM + k0 + cc];
            sA[r * LDA + cc] = wmma::__float_to_tf32(v);
        }
        for (int idx = tid; idx < KC * BN; idx += 256) {
            int r = idx >> 6, cc = idx & 63;
            sB[r * LDB + cc] =
                wmma::__float_to_tf32(W1e[(size_t)(k0 + r) * HID + n0 + cc]);
        }
        __syncthreads();
#pragma unroll
        for (int ks = 0; ks < KC / 8; ks++) {
            wmma::fragment<wmma::matrix_a, 16, 16, 8, wmma::precision::tf32, wmma::row_major> a[2];
            wmma::fragment<wmma::matrix_b, 16, 16, 8, wmma::precision::tf32, wmma::row_major> b[2];
            wmma::load_matrix_sync(a[0], sA + wm * LDA + ks * 8, LDA);
            wmma::load_matrix_sync(a[1], sA + (wm + 16) * LDA + ks * 8, LDA);
            wmma::load_matrix_sync(b[0], sB + ks * 8 * LDB + wn, LDB);
            wmma::load_matrix_sync(b[1], sB + ks * 8 * LDB + wn + 16, LDB);
#pragma unroll
            for (int i = 0; i < 2; i++)
#pragma unroll
                for (int j = 0; j < 2; j++)
                    wmma::mma_sync(c[i][j], a[i], b[j], c[i][j]);
        }
        __syncthreads();
    }

    float* sOut = smem;
#pragma unroll
    for (int i = 0; i < 2; i++)
#pragma unroll
        for (int j = 0; j < 2; j++)
            wmma::store_matrix_sync(sOut + (wm + i * 16) * LDO + wn + j * 16,
                                    c[i][j], LDO, wmma::mem_row_major);
    __syncthreads();

    const float* b1e = b1 + e * HID;
    for (int idx = tid; idx < BM * BN; idx += 256) {
        int r = idx >> 6, cc = idx & 63;
        int entry = sEntry[r];
        if (entry >= 0) {
            float v = sOut[r * LDO + cc] + b1e[n0 + cc];
            float g = 0.5f * v * (1.0f + erff(v * 0.70710678118654752f));  // exact GELU
            g_h[(size_t)entry * HID + n0 + cc] = wmma::__float_to_tf32(g);
        }
    }
}

// GEMM2: y[pair] = (gather(h) @ W2[e] + b2[e]) * gate(pair)
__global__ void __launch_bounds__(256)
gemm2_kernel(const float* __restrict__ W2,
             const float* __restrict__ b2) {
    const int e  = blockIdx.z;
    const int M  = g_counts[e];
    const int m0 = blockIdx.x * BM;
    if (m0 >= M) return;
    const int n0 = blockIdx.y * BN;

    __shared__ __align__(32) float smem[BM * LDO];
    float* sA = smem;
    float* sB = smem + BM * LDA;
    __shared__ int sEntry[BM];

    const int tid = threadIdx.x;
    if (tid < BM) {
        int r = m0 + tid;
        sEntry[tid] = (r < M) ? g_list[e * NTOK + r] : -1;
    }
    __syncthreads();

    const float* W2e = W2 + (size_t)e * HID * OUTD;

    wmma::fragment<wmma::accumulator, 16, 16, 8, float> c[2][2];
#pragma unroll
    for (int i = 0; i < 2; i++)
#pragma unroll
        for (int j = 0; j < 2; j++) wmma::fill_fragment(c[i][j], 0.f);

    const int w  = tid >> 5;
    const int wm = (w & 3) * 32;
    const int wn = (w >> 2) * 32;

    for (int k0 = 0; k0 < HID; k0 += KC) {
        for (int idx = tid; idx < BM * KC; idx += 256) {
            int r = idx >> 5, cc = idx & 31;
            int entry = sEntry[r];
            float v = 0.f;
            if (entry >= 0) v = g_h[(size_t)entry * HID + k0 + cc];  // already tf32
            sA[r * LDA + cc] = v;
        }
        for (int idx = tid; idx < KC * BN; idx += 256) {
            int r = idx >> 6, cc = idx & 63;
            sB[r * LDB + cc] =
                wmma::__float_to_tf32(W2e[(size_t)(k0 + r) * OUTD + n0 + cc]);
        }
        __syncthreads();
#pragma unroll
        for (int ks = 0; ks < KC / 8; ks++) {
            wmma::fragment<wmma::matrix_a, 16, 16, 8, wmma::precision::tf32, wmma::row_major> a[2];
            wmma::fragment<wmma::matrix_b, 16, 16, 8, wmma::precision::tf32, wmma::row_major> b[2];
            wmma::load_matrix_sync(a[0], sA + wm * LDA + ks * 8, LDA);
            wmma::load_matrix_sync(a[1], sA + (wm + 16) * LDA + ks * 8, LDA);
            wmma::load_matrix_sync(b[0], sB + ks * 8 * LDB + wn, LDB);
            wmma::load_matrix_sync(b[1], sB + ks * 8 * LDB + wn + 16, LDB);
#pragma unroll
            for (int i = 0; i < 2; i++)
#pragma unroll
                for (int j = 0; j < 2; j++)
                    wmma::mma_sync(c[i][j], a[i], b[j], c[i][j]);
        }
        __syncthreads();
    }

    float* sOut = smem;
#pragma unroll
    for (int i = 0; i < 2; i++)
#pragma unroll
        for (int j = 0; j < 2; j++)
            wmma::store_matrix_sync(sOut + (wm + i * 16) * LDO + wn + j * 16,
                                    c[i][j], LDO, wmma::mem_row_major);
    __syncthreads();

    const float* b2e = b2 + e * OUTD;
    for (int idx = tid; idx < BM * BN; idx += 256) {
        int r = idx >> 6, cc = idx & 63;
        int entry = sEntry[r];
        if (entry >= 0) {
            float v = sOut[r * LDO + cc] + b2e[n0 + cc];
            int tok = entry >> 1;
            float2 gg = g_gates[tok];
            float gate = (entry & 1) ? gg.y : gg.x;
            g_y[(size_t)entry * OUTD + n0 + cc] = v * gate;
        }
    }
}

__global__ void combine_kernel(float* __restrict__ out) {
    int i = blockIdx.x * blockDim.x + threadIdx.x;
    if (i >= NTOK * OUTD) return;
    int t = i / OUTD;
    int o = i - t * OUTD;
    out[i] = g_y[(size_t)(2 * t) * OUTD + o] + g_y[(size_t)(2 * t + 1) * OUTD + o];
}

// ---------------- launch ----------------
extern "C" void kernel_launch(void* const* d_in, const int* in_sizes, int n_in,
                              void* d_out, int out_size) {
    const float* x  = (const float*)d_in[0];
    const float* Wg = (const float*)d_in[1];
    const float* bg = (const float*)d_in[2];
    const float* W1 = (const float*)d_in[3];
    const float* b1 = (const float*)d_in[4];
    const float* W2 = (const float*)d_in[5];
    const float* b2 = (const float*)d_in[6];
    float* out = (float*)d_out;

    zero_counts_kernel<<<1, 32>>>();
    router_kernel<<<(NTOK * 32) / 256, 256>>>(x, Wg, bg);
    gemm1_kernel<<<dim3(NTOK / BM, HID / BN, NEXP), 256>>>(x, W1, b1);
    gemm2_kernel<<<dim3(NTOK / BM, OUTD / BN, NEXP), 256>>>(W2, b2);
    combine_kernel<<<(NTOK * OUTD + 255) / 256, 256>>>(out);
}